// round 16
// baseline (speedup 1.0000x reference)
#include <cuda_runtime.h>
#include <cuda_fp16.h>
#include <math.h>
#include <stdint.h>

#define Nn 256
#define Mm 32768
#define Dd 384
#define ALPHA 20.0f
#define STOPTHR 0.005f
#define LOG_A (-5.545177444479562f)   /* log(1/256 + 1e-30) */
#define LOG_B (-10.397207708399179f)  /* log(1/32768 + 1e-30) */
#define AA 0.00390625f
#define BB 3.0517578125e-05f
#define NEGBIG (-3.0e38f)

#define NB 128           /* persistent grid: 128 blocks x 256 threads = 32768 threads */
#define NT 256

// ---------------- device state (scratch) ----------------
__device__ float    g_logK0[(size_t)Nn * Mm];   // 33.5 MB, L2-resident
__device__ __half   g_xh[(size_t)Nn * Dd];
__device__ __half   g_xl[(size_t)Nn * Dd];
__device__ __half   g_yh[(size_t)Mm * Dd];      // 25 MB
__device__ __half   g_yl[(size_t)Mm * Dd];      // 25 MB
__device__ float    g_xn[Nn];
__device__ float    g_yn[Mm];
__device__ float    g_logu[Nn];
__device__ float    g_logv[Mm];
__device__ float    g_cumu[Nn];
__device__ float    g_cumv[Mm];
__device__ unsigned g_errbits;                  // float bits, atomicMax (vals >= 0)
__device__ volatile unsigned g_barcnt;          // grid barrier monotonic counter

// ---------------- helpers ----------------
__device__ __forceinline__ uint32_t smem_u32(const void* p) {
    uint32_t a;
    asm("{ .reg .u64 t; cvta.to.shared.u64 t, %1; cvt.u32.u64 %0, t; }" : "=r"(a) : "l"(p));
    return a;
}
__device__ __forceinline__ void cp16(uint32_t dst, const void* src) {
    asm volatile("cp.async.cg.shared.global [%0], [%1], 16;" :: "r"(dst), "l"(src));
}
#define CP_COMMIT() asm volatile("cp.async.commit_group;" ::: "memory")
#define CP_WAIT2()  asm volatile("cp.async.wait_group 2;" ::: "memory")
#define CP_WAIT1()  asm volatile("cp.async.wait_group 1;" ::: "memory")
#define CP_WAIT0()  asm volatile("cp.async.wait_group 0;" ::: "memory")

__device__ __forceinline__ void ldmx4(uint32_t& r0, uint32_t& r1, uint32_t& r2,
                                      uint32_t& r3, uint32_t addr) {
    asm volatile("ldmatrix.sync.aligned.m8n8.x4.shared.b16 {%0,%1,%2,%3}, [%4];"
                 : "=r"(r0), "=r"(r1), "=r"(r2), "=r"(r3) : "r"(addr));
}
__device__ __forceinline__ void mma16816(float* c, uint32_t a0, uint32_t a1, uint32_t a2,
                                         uint32_t a3, uint32_t b0, uint32_t b1) {
    asm volatile(
        "mma.sync.aligned.m16n8k16.row.col.f32.f16.f16.f32 "
        "{%0,%1,%2,%3}, {%4,%5,%6,%7}, {%8,%9}, {%0,%1,%2,%3};"
        : "+f"(c[0]), "+f"(c[1]), "+f"(c[2]), "+f"(c[3])
        : "r"(a0), "r"(a1), "r"(a2), "r"(a3), "r"(b0), "r"(b1));
}

// ---------------- init ----------------
__global__ void k_init(float* out) {
    int idx = blockIdx.x * blockDim.x + threadIdx.x;
    if (idx < Mm) { g_logv[idx] = 0.f; g_cumv[idx] = 0.f; }
    if (idx < Nn) { g_logu[idx] = 0.f; g_cumu[idx] = 0.f; }
    if (idx == 0) { g_errbits = 0u; g_barcnt = 0u; out[0] = 0.f; }
}

// ---------------- fused norm + fp16 hi/lo split (warp per row) ----------------
__global__ void k_prep(const float* __restrict__ src, __half* __restrict__ hi,
                       __half* __restrict__ lo, float* __restrict__ norm) {
    int row  = blockIdx.x * 8 + (threadIdx.x >> 5);
    int lane = threadIdx.x & 31;
    const float4* sp = (const float4*)(src + (size_t)row * Dd);
    uint2* hp = (uint2*)(hi + (size_t)row * Dd);
    uint2* lp = (uint2*)(lo + (size_t)row * Dd);
    float s = 0.f;
    #pragma unroll
    for (int it = 0; it < 3; it++) {
        float4 v = sp[lane + it * 32];
        s = fmaf(v.x, v.x, fmaf(v.y, v.y, fmaf(v.z, v.z, fmaf(v.w, v.w, s))));
        __half h0 = __float2half_rn(v.x), h1 = __float2half_rn(v.y);
        __half h2 = __float2half_rn(v.z), h3 = __float2half_rn(v.w);
        __half l0 = __float2half_rn(v.x - __half2float(h0));
        __half l1 = __float2half_rn(v.y - __half2float(h1));
        __half l2 = __float2half_rn(v.z - __half2float(h2));
        __half l3 = __float2half_rn(v.w - __half2float(h3));
        __half2 ph0 = __halves2half2(h0, h1), ph1 = __halves2half2(h2, h3);
        __half2 pl0 = __halves2half2(l0, l1), pl1 = __halves2half2(l2, l3);
        uint2 hw, lw;
        hw.x = *(uint32_t*)&ph0; hw.y = *(uint32_t*)&ph1;
        lw.x = *(uint32_t*)&pl0; lw.y = *(uint32_t*)&pl1;
        hp[lane + it * 32] = hw;
        lp[lane + it * 32] = lw;
    }
    #pragma unroll
    for (int o = 16; o; o >>= 1) s += __shfl_xor_sync(0xffffffffu, s, o);
    if (lane == 0) norm[row] = s;
}

// ---------------- tensor-core (mma.sync) logK0 GEMM, 4-stage + ldmatrix ----------------
#define ASTRIDE 24
#define BUFB (128 * ASTRIDE * 2)   /* bytes per buffer = 6144 */
#define STAGES 4
#define KSTEPS 72

__device__ __forceinline__ void gemm_load(int s, int i0, int j0, uint32_t sbA,
                                          uint32_t sbB, uint32_t aoff,
                                          int lrow, int lseg) {
    int p = s / 24;
    int kk = (s % 24) * 16;
    const __half* Aarr = (p == 2) ? g_xl : g_xh;
    const __half* Barr = (p == 1) ? g_yl : g_yh;
    int b = s % STAGES;
    cp16(sbA + b * BUFB + aoff, Aarr + (size_t)(i0 + lrow) * Dd + kk + lseg * 8);
    cp16(sbB + b * BUFB + aoff, Barr + (size_t)(j0 + lrow) * Dd + kk + lseg * 8);
}

__global__ void __launch_bounds__(256, 3) k_gemm_mma() {
    __shared__ __half As[STAGES][128 * ASTRIDE];
    __shared__ __half Bs[STAGES][128 * ASTRIDE];
    int tid = threadIdx.x;
    int wid = tid >> 5, lane = tid & 31;
    int wr = wid >> 2, wc = wid & 3;          // warp grid 2x4
    int g = lane >> 2, q = lane & 3;
    int i0 = blockIdx.y * 128;                // over Nn
    int j0 = blockIdx.x * 128;                // over Mm

    uint32_t sbA = smem_u32(As);
    uint32_t sbB = smem_u32(Bs);
    int lrow = tid >> 1;                      // 0..127
    int lseg = tid & 1;
    uint32_t aoff = (uint32_t)(lrow * ASTRIDE + lseg * 8) * 2;

    uint32_t a_frag_off = (uint32_t)(((wr * 64) + (lane & 15)) * ASTRIDE
                                     + (lane >> 4) * 8) * 2;
    uint32_t b_frag_off = (uint32_t)(((wc * 32) + ((lane >> 4) * 8) + (lane & 7)) * ASTRIDE
                                     + ((lane >> 3) & 1) * 8) * 2;

    float acc[4][4][4];
    #pragma unroll
    for (int a = 0; a < 4; a++)
        #pragma unroll
        for (int b = 0; b < 4; b++)
            #pragma unroll
            for (int c = 0; c < 4; c++) acc[a][b][c] = 0.f;

    gemm_load(0, i0, j0, sbA, sbB, aoff, lrow, lseg); CP_COMMIT();
    gemm_load(1, i0, j0, sbA, sbB, aoff, lrow, lseg); CP_COMMIT();
    gemm_load(2, i0, j0, sbA, sbB, aoff, lrow, lseg); CP_COMMIT();

    #pragma unroll 1
    for (int s = 0; s < KSTEPS; s++) {
        if (s < KSTEPS - 2)      { CP_WAIT2(); }
        else if (s == KSTEPS - 2){ CP_WAIT1(); }
        else                     { CP_WAIT0(); }
        __syncthreads();

        int buf = s % STAGES;
        uint32_t abase = sbA + buf * BUFB + a_frag_off;
        uint32_t bbase = sbB + buf * BUFB + b_frag_off;

        uint32_t b0[4], b1[4];
        ldmx4(b0[0], b1[0], b0[1], b1[1], bbase);
        ldmx4(b0[2], b1[2], b0[3], b1[3], bbase + 16 * ASTRIDE * 2);

        #pragma unroll
        for (int tm = 0; tm < 4; tm++) {
            uint32_t a0, a1, a2, a3;
            ldmx4(a0, a1, a2, a3, abase + tm * (16 * ASTRIDE * 2));
            #pragma unroll
            for (int tn = 0; tn < 4; tn++)
                mma16816(acc[tm][tn], a0, a1, a2, a3, b0[tn], b1[tn]);
        }

        if (s + 3 < KSTEPS) {
            gemm_load(s + 3, i0, j0, sbA, sbB, aoff, lrow, lseg);
            CP_COMMIT();
        }
    }

    #pragma unroll
    for (int tm = 0; tm < 4; tm++) {
        int r0 = i0 + wr * 64 + tm * 16 + g;
        float xn0 = g_xn[r0], xn1 = g_xn[r0 + 8];
        #pragma unroll
        for (int tn = 0; tn < 4; tn++) {
            int cb = j0 + wc * 32 + tn * 8 + q * 2;
            float yn0 = g_yn[cb], yn1 = g_yn[cb + 1];
            float2 o0, o1;
            o0.x = fmaf(2.f * ALPHA, acc[tm][tn][0], -ALPHA * (xn0 + yn0));
            o0.y = fmaf(2.f * ALPHA, acc[tm][tn][1], -ALPHA * (xn0 + yn1));
            o1.x = fmaf(2.f * ALPHA, acc[tm][tn][2], -ALPHA * (xn1 + yn0));
            o1.y = fmaf(2.f * ALPHA, acc[tm][tn][3], -ALPHA * (xn1 + yn1));
            *(float2*)(g_logK0 + (size_t)r0 * Mm + cb)       = o0;
            *(float2*)(g_logK0 + (size_t)(r0 + 8) * Mm + cb) = o1;
        }
    }
}

// ============ persistent Sinkhorn (+ fused transp/loss) ============

__device__ __forceinline__ void gridbar(unsigned& epoch) {
    epoch += NB;
    __syncthreads();
    if (threadIdx.x == 0) {
        __threadfence();
        atomicAdd((unsigned*)&g_barcnt, 1u);
        while (g_barcnt < epoch) { }
        __threadfence();
    }
    __syncthreads();
}

// online-LSE update: (m, s) <- combine with value t
#define ONLINE(m, s, t) do { \
    float _n = fmaxf(m, t); \
    s = fmaf(s, __expf((m) - _n), __expf((t) - _n)); \
    m = _n; } while (0)

// combine two (m, s) LSE pairs into the first
__device__ __forceinline__ void lse_comb(float& m, float& s, float om, float os) {
    float nm = fmaxf(m, om);
    s = fmaf(s, __expf(m - nm), os * __expf(om - nm));
    m = nm;
}

#define SHFL_ADD4(m, o) do { \
    m.x += __shfl_xor_sync(0xffffffffu, m.x, o); \
    m.y += __shfl_xor_sync(0xffffffffu, m.y, o); \
    m.z += __shfl_xor_sync(0xffffffffu, m.z, o); \
    m.w += __shfl_xor_sync(0xffffffffu, m.w, o); } while (0)
#define SHFL_LSE4(m, s, o) do { \
    float _om, _os; \
    _om = __shfl_xor_sync(0xffffffffu, m.x, o); _os = __shfl_xor_sync(0xffffffffu, s.x, o); lse_comb(m.x, s.x, _om, _os); \
    _om = __shfl_xor_sync(0xffffffffu, m.y, o); _os = __shfl_xor_sync(0xffffffffu, s.y, o); lse_comb(m.y, s.y, _om, _os); \
    _om = __shfl_xor_sync(0xffffffffu, m.z, o); _os = __shfl_xor_sync(0xffffffffu, s.z, o); lse_comb(m.z, s.z, _om, _os); \
    _om = __shfl_xor_sync(0xffffffffu, m.w, o); _os = __shfl_xor_sync(0xffffffffu, s.w, o); lse_comb(m.w, s.w, _om, _os); } while (0)

// logv <- LOG_B - lse_i(logK0 + logu). ONE matrix read (online LSE).
// 4 lanes share col-group cg (4 cols via float4); lane p owns rows p*64..p*64+63.
__device__ __forceinline__ void colpass(float* su) {
    int tid = threadIdx.x;
    su[tid] = g_logu[tid];
    __syncthreads();
    int g = blockIdx.x * NT + tid;
    int cg = g >> 2, p = g & 3;
    const float4* col = (const float4*)g_logK0 + cg;
    int ibase = p * 64;

    float4 m = {NEGBIG, NEGBIG, NEGBIG, NEGBIG};
    float4 s = {0.f, 0.f, 0.f, 0.f};
    #pragma unroll 8
    for (int ii = 0; ii < 64; ii++) {
        float4 v = col[(size_t)(ibase + ii) * (Mm / 4)];
        float u = su[ibase + ii];
        ONLINE(m.x, s.x, v.x + u); ONLINE(m.y, s.y, v.y + u);
        ONLINE(m.z, s.z, v.z + u); ONLINE(m.w, s.w, v.w + u);
    }
    SHFL_LSE4(m, s, 1); SHFL_LSE4(m, s, 2);

    if (p == 0) {
        float4 o;
        o.x = LOG_B - (m.x + logf(s.x));
        o.y = LOG_B - (m.y + logf(s.y));
        o.z = LOG_B - (m.z + logf(s.z));
        o.w = LOG_B - (m.w + logf(s.w));
        ((float4*)g_logv)[cg] = o;
    }
    __syncthreads();
}

// logu <- LOG_A - lse_j(logK0 + logv). ONE matrix read (online LSE), 2 rows/block.
__device__ __forceinline__ void rowpass(float* red) {
    int tid = threadIdx.x;
    int i0 = blockIdx.x * 2;
    const float4* r0 = (const float4*)(g_logK0 + (size_t)i0 * Mm);
    const float4* r1 = (const float4*)(g_logK0 + (size_t)(i0 + 1) * Mm);
    const float4* vv = (const float4*)g_logv;
    const int NV = Mm / 4;

    float4 m0 = {NEGBIG, NEGBIG, NEGBIG, NEGBIG}, s0 = {0.f, 0.f, 0.f, 0.f};
    float4 m1 = m0, s1 = s0;
    #pragma unroll 4
    for (int j = tid; j < NV; j += NT) {
        float4 v = vv[j], a = r0[j], b = r1[j];
        ONLINE(m0.x, s0.x, a.x + v.x); ONLINE(m0.y, s0.y, a.y + v.y);
        ONLINE(m0.z, s0.z, a.z + v.z); ONLINE(m0.w, s0.w, a.w + v.w);
        ONLINE(m1.x, s1.x, b.x + v.x); ONLINE(m1.y, s1.y, b.y + v.y);
        ONLINE(m1.z, s1.z, b.z + v.z); ONLINE(m1.w, s1.w, b.w + v.w);
    }
    // merge components
    float M0 = m0.x, S0 = s0.x;
    lse_comb(M0, S0, m0.y, s0.y); lse_comb(M0, S0, m0.z, s0.z); lse_comb(M0, S0, m0.w, s0.w);
    float M1 = m1.x, S1 = s1.x;
    lse_comb(M1, S1, m1.y, s1.y); lse_comb(M1, S1, m1.z, s1.z); lse_comb(M1, S1, m1.w, s1.w);
    // warp reduce
    #pragma unroll
    for (int o = 16; o; o >>= 1) {
        float om, os;
        om = __shfl_xor_sync(0xffffffffu, M0, o); os = __shfl_xor_sync(0xffffffffu, S0, o);
        lse_comb(M0, S0, om, os);
        om = __shfl_xor_sync(0xffffffffu, M1, o); os = __shfl_xor_sync(0xffffffffu, S1, o);
        lse_comb(M1, S1, om, os);
    }
    int w = tid >> 5;
    if ((tid & 31) == 0) {
        red[w] = M0; red[8 + w] = S0; red[16 + w] = M1; red[24 + w] = S1;
    }
    __syncthreads();
    if (tid == 0) {
        float Ma = red[0], Sa = red[8];
        float Mb = red[16], Sb = red[24];
        #pragma unroll
        for (int k = 1; k < 8; k++) {
            lse_comb(Ma, Sa, red[k], red[8 + k]);
            lse_comb(Mb, Sb, red[16 + k], red[24 + k]);
        }
        g_logu[i0]     = LOG_A - (Ma + logf(Sa));
        g_logu[i0 + 1] = LOG_A - (Mb + logf(Sb));
    }
    __syncthreads();
}

// Column-marginal error + transp + loss, ONE matrix read, no max-shift:
// log t = logK0 + su_i + sv_j is bounded (t sums to marginals) => direct exp.
// col marginal = sum_i t_ij; err = |sum - BB|. transp stores SCALAR (out+1 is
// only 4-byte aligned).
__device__ __forceinline__ float colerr_transp(float* su, float* out, int do_err) {
    int tid = threadIdx.x;
    su[tid] = g_cumu[tid] + g_logu[tid];
    __syncthreads();
    int g = blockIdx.x * NT + tid;
    int cg = g >> 2, p = g & 3;
    const float4* col = (const float4*)g_logK0 + cg;
    float* outp = out + 1 + cg * 4;
    int ibase = p * 64;

    float4 cv = ((const float4*)g_cumv)[cg];
    float4 lv = ((const float4*)g_logv)[cg];
    float4 sv;
    sv.x = cv.x + lv.x; sv.y = cv.y + lv.y; sv.z = cv.z + lv.z; sv.w = cv.w + lv.w;

    float4 s = {0.f, 0.f, 0.f, 0.f};
    float part = 0.f;
    #pragma unroll 4
    for (int ii = 0; ii < 64; ii++) {
        float4 v = col[(size_t)(ibase + ii) * (Mm / 4)];
        float u = su[ibase + ii];
        float4 tr;
        tr.x = __expf(v.x + u + sv.x); tr.y = __expf(v.y + u + sv.y);
        tr.z = __expf(v.z + u + sv.z); tr.w = __expf(v.w + u + sv.w);
        s.x += tr.x; s.y += tr.y; s.z += tr.z; s.w += tr.w;
        float* op = outp + (size_t)(ibase + ii) * Mm;
        op[0] = tr.x; op[1] = tr.y; op[2] = tr.z; op[3] = tr.w;
        part = fmaf(tr.x, v.x, fmaf(tr.y, v.y, fmaf(tr.z, v.z, fmaf(tr.w, v.w, part))));
    }
    SHFL_ADD4(s, 1); SHFL_ADD4(s, 2);

    if (do_err) {
        float d = fmaxf(fmaxf(fabsf(s.x - BB), fabsf(s.y - BB)),
                        fmaxf(fabsf(s.z - BB), fabsf(s.w - BB)));
        #pragma unroll
        for (int o = 16; o; o >>= 1)
            d = fmaxf(d, __shfl_xor_sync(0xffffffffu, d, o));
        if ((tid & 31) == 0) atomicMax(&g_errbits, __float_as_uint(d));
    }
    __syncthreads();
    return part * (-1.f / ALPHA);
}

__global__ void __launch_bounds__(NT, 1) k_sink(float* out) {
    __shared__ float su[Nn];
    __shared__ float red[32];
    unsigned epoch = 0;
    int tid = threadIdx.x;
    int gtid = blockIdx.x * NT + tid;
    float part = 0.f;
    int conv = 0;

    for (int t = 1; t <= 100; t++) {
        colpass(su);
        gridbar(epoch);
        rowpass(red);
        gridbar(epoch);
        if (t % 50 == 1) {
            part = colerr_transp(su, out, 1);       // speculative transp + err
            gridbar(epoch);
            conv = (__uint_as_float(*(volatile unsigned*)&g_errbits) <= STOPTHR);
            if (conv) break;
            g_cumv[gtid] += g_logv[gtid]; g_logv[gtid] = 0.f;
            if (gtid < Nn) { g_cumu[gtid] += g_logu[gtid]; g_logu[gtid] = 0.f; }
            if (gtid == 0) g_errbits = 0u;
            gridbar(epoch);
        }
    }
    if (!conv)
        part = colerr_transp(su, out, 0);           // final state transp

    #pragma unroll
    for (int o = 16; o; o >>= 1) part += __shfl_xor_sync(0xffffffffu, part, o);
    if ((tid & 31) == 0) red[tid >> 5] = part;
    __syncthreads();
    if (tid == 0) {
        float S = 0.f;
        #pragma unroll
        for (int w = 0; w < 8; w++) S += red[w];
        atomicAdd(out, S);
    }
}

// ---------------- launch ----------------
extern "C" void kernel_launch(void* const* d_in, const int* in_sizes, int n_in,
                              void* d_out, int out_size) {
    const float* x = (const float*)d_in[0];   // [256, 384]
    const float* y = (const float*)d_in[1];   // [32768, 384]
    float* out = (float*)d_out;               // [0]=loss, [1..]=transp

    __half *xh, *xl, *yh, *yl;
    float *xn, *yn;
    cudaGetSymbolAddress((void**)&xh, g_xh);
    cudaGetSymbolAddress((void**)&xl, g_xl);
    cudaGetSymbolAddress((void**)&yh, g_yh);
    cudaGetSymbolAddress((void**)&yl, g_yl);
    cudaGetSymbolAddress((void**)&xn, g_xn);
    cudaGetSymbolAddress((void**)&yn, g_yn);

    k_init<<<(Mm + 255) / 256, 256>>>(out);
    k_prep<<<Nn / 8, 256>>>(x, xh, xl, xn);
    k_prep<<<Mm / 8, 256>>>(y, yh, yl, yn);
    k_gemm_mma<<<dim3(Mm / 128, Nn / 128), 256>>>();
    k_sink<<<NB, NT>>>(out);
}

// round 17
// speedup vs baseline: 1.5309x; 1.5309x over previous
#include <cuda_runtime.h>
#include <cuda_fp16.h>
#include <math.h>
#include <stdint.h>

#define Nn 256
#define Mm 32768
#define Dd 384
#define ALPHA 20.0f
#define STOPTHR 0.005f
#define LOG_A (-5.545177444479562f)   /* log(1/256 + 1e-30) */
#define LOG_B (-10.397207708399179f)  /* log(1/32768 + 1e-30) */
#define AA 0.00390625f
#define BB 3.0517578125e-05f
#define NEGBIG (-3.0e38f)

#define NB 128           /* persistent grid: 128 blocks x 256 threads = 32768 threads */
#define NT 256

// ---------------- device state (scratch) ----------------
__device__ float    g_logK0[(size_t)Nn * Mm];   // 33.5 MB, L2-resident
__device__ __half   g_xh[(size_t)Nn * Dd];
__device__ __half   g_xl[(size_t)Nn * Dd];
__device__ __half   g_yh[(size_t)Mm * Dd];      // 25 MB
__device__ __half   g_yl[(size_t)Mm * Dd];      // 25 MB
__device__ float    g_xn[Nn];
__device__ float    g_yn[Mm];
__device__ float    g_logu[Nn];
__device__ float    g_logv[Mm];
__device__ float    g_cumu[Nn];
__device__ float    g_cumv[Mm];
__device__ unsigned g_errbits;                  // float bits, atomicMax (vals >= 0)
__device__ volatile unsigned g_barcnt;          // grid barrier monotonic counter

// ---------------- helpers ----------------
__device__ __forceinline__ uint32_t smem_u32(const void* p) {
    uint32_t a;
    asm("{ .reg .u64 t; cvta.to.shared.u64 t, %1; cvt.u32.u64 %0, t; }" : "=r"(a) : "l"(p));
    return a;
}
__device__ __forceinline__ void cp16(uint32_t dst, const void* src) {
    asm volatile("cp.async.cg.shared.global [%0], [%1], 16;" :: "r"(dst), "l"(src));
}
#define CP_COMMIT() asm volatile("cp.async.commit_group;" ::: "memory")
#define CP_WAIT2()  asm volatile("cp.async.wait_group 2;" ::: "memory")
#define CP_WAIT1()  asm volatile("cp.async.wait_group 1;" ::: "memory")
#define CP_WAIT0()  asm volatile("cp.async.wait_group 0;" ::: "memory")

__device__ __forceinline__ void ldmx4(uint32_t& r0, uint32_t& r1, uint32_t& r2,
                                      uint32_t& r3, uint32_t addr) {
    asm volatile("ldmatrix.sync.aligned.m8n8.x4.shared.b16 {%0,%1,%2,%3}, [%4];"
                 : "=r"(r0), "=r"(r1), "=r"(r2), "=r"(r3) : "r"(addr));
}
__device__ __forceinline__ void mma16816(float* c, uint32_t a0, uint32_t a1, uint32_t a2,
                                         uint32_t a3, uint32_t b0, uint32_t b1) {
    asm volatile(
        "mma.sync.aligned.m16n8k16.row.col.f32.f16.f16.f32 "
        "{%0,%1,%2,%3}, {%4,%5,%6,%7}, {%8,%9}, {%0,%1,%2,%3};"
        : "+f"(c[0]), "+f"(c[1]), "+f"(c[2]), "+f"(c[3])
        : "r"(a0), "r"(a1), "r"(a2), "r"(a3), "r"(b0), "r"(b1));
}

// ---------------- init ----------------
__global__ void k_init(float* out) {
    int idx = blockIdx.x * blockDim.x + threadIdx.x;
    if (idx < Mm) { g_logv[idx] = 0.f; g_cumv[idx] = 0.f; }
    if (idx < Nn) { g_logu[idx] = 0.f; g_cumu[idx] = 0.f; }
    if (idx == 0) { g_errbits = 0u; g_barcnt = 0u; out[0] = 0.f; }
}

// ---------------- fused norm + fp16 hi/lo split (warp per row) ----------------
__global__ void k_prep(const float* __restrict__ src, __half* __restrict__ hi,
                       __half* __restrict__ lo, float* __restrict__ norm) {
    int row  = blockIdx.x * 8 + (threadIdx.x >> 5);
    int lane = threadIdx.x & 31;
    const float4* sp = (const float4*)(src + (size_t)row * Dd);
    uint2* hp = (uint2*)(hi + (size_t)row * Dd);
    uint2* lp = (uint2*)(lo + (size_t)row * Dd);
    float s = 0.f;
    #pragma unroll
    for (int it = 0; it < 3; it++) {
        float4 v = sp[lane + it * 32];
        s = fmaf(v.x, v.x, fmaf(v.y, v.y, fmaf(v.z, v.z, fmaf(v.w, v.w, s))));
        __half h0 = __float2half_rn(v.x), h1 = __float2half_rn(v.y);
        __half h2 = __float2half_rn(v.z), h3 = __float2half_rn(v.w);
        __half l0 = __float2half_rn(v.x - __half2float(h0));
        __half l1 = __float2half_rn(v.y - __half2float(h1));
        __half l2 = __float2half_rn(v.z - __half2float(h2));
        __half l3 = __float2half_rn(v.w - __half2float(h3));
        __half2 ph0 = __halves2half2(h0, h1), ph1 = __halves2half2(h2, h3);
        __half2 pl0 = __halves2half2(l0, l1), pl1 = __halves2half2(l2, l3);
        uint2 hw, lw;
        hw.x = *(uint32_t*)&ph0; hw.y = *(uint32_t*)&ph1;
        lw.x = *(uint32_t*)&pl0; lw.y = *(uint32_t*)&pl1;
        hp[lane + it * 32] = hw;
        lp[lane + it * 32] = lw;
    }
    #pragma unroll
    for (int o = 16; o; o >>= 1) s += __shfl_xor_sync(0xffffffffu, s, o);
    if (lane == 0) norm[row] = s;
}

// ---------------- tensor-core (mma.sync) logK0 GEMM, 4-stage + ldmatrix ----------------
#define ASTRIDE 24
#define BUFB (128 * ASTRIDE * 2)   /* bytes per buffer = 6144 */
#define STAGES 4
#define KSTEPS 72

__device__ __forceinline__ void gemm_load(int s, int i0, int j0, uint32_t sbA,
                                          uint32_t sbB, uint32_t aoff,
                                          int lrow, int lseg) {
    int p = s / 24;
    int kk = (s % 24) * 16;
    const __half* Aarr = (p == 2) ? g_xl : g_xh;
    const __half* Barr = (p == 1) ? g_yl : g_yh;
    int b = s % STAGES;
    cp16(sbA + b * BUFB + aoff, Aarr + (size_t)(i0 + lrow) * Dd + kk + lseg * 8);
    cp16(sbB + b * BUFB + aoff, Barr + (size_t)(j0 + lrow) * Dd + kk + lseg * 8);
}

__global__ void __launch_bounds__(256) k_gemm_mma() {
    __shared__ __half As[STAGES][128 * ASTRIDE];
    __shared__ __half Bs[STAGES][128 * ASTRIDE];
    int tid = threadIdx.x;
    int wid = tid >> 5, lane = tid & 31;
    int wr = wid >> 2, wc = wid & 3;          // warp grid 2x4
    int g = lane >> 2, q = lane & 3;
    int i0 = blockIdx.y * 128;                // over Nn
    int j0 = blockIdx.x * 128;                // over Mm

    uint32_t sbA = smem_u32(As);
    uint32_t sbB = smem_u32(Bs);
    int lrow = tid >> 1;                      // 0..127
    int lseg = tid & 1;
    uint32_t aoff = (uint32_t)(lrow * ASTRIDE + lseg * 8) * 2;

    uint32_t a_frag_off = (uint32_t)(((wr * 64) + (lane & 15)) * ASTRIDE
                                     + (lane >> 4) * 8) * 2;
    uint32_t b_frag_off = (uint32_t)(((wc * 32) + ((lane >> 4) * 8) + (lane & 7)) * ASTRIDE
                                     + ((lane >> 3) & 1) * 8) * 2;

    float acc[4][4][4];
    #pragma unroll
    for (int a = 0; a < 4; a++)
        #pragma unroll
        for (int b = 0; b < 4; b++)
            #pragma unroll
            for (int c = 0; c < 4; c++) acc[a][b][c] = 0.f;

    gemm_load(0, i0, j0, sbA, sbB, aoff, lrow, lseg); CP_COMMIT();
    gemm_load(1, i0, j0, sbA, sbB, aoff, lrow, lseg); CP_COMMIT();
    gemm_load(2, i0, j0, sbA, sbB, aoff, lrow, lseg); CP_COMMIT();

    #pragma unroll 1
    for (int s = 0; s < KSTEPS; s++) {
        if (s < KSTEPS - 2)      { CP_WAIT2(); }
        else if (s == KSTEPS - 2){ CP_WAIT1(); }
        else                     { CP_WAIT0(); }
        __syncthreads();

        int buf = s % STAGES;
        uint32_t abase = sbA + buf * BUFB + a_frag_off;
        uint32_t bbase = sbB + buf * BUFB + b_frag_off;

        uint32_t b0[4], b1[4];
        ldmx4(b0[0], b1[0], b0[1], b1[1], bbase);
        ldmx4(b0[2], b1[2], b0[3], b1[3], bbase + 16 * ASTRIDE * 2);

        #pragma unroll
        for (int tm = 0; tm < 4; tm++) {
            uint32_t a0, a1, a2, a3;
            ldmx4(a0, a1, a2, a3, abase + tm * (16 * ASTRIDE * 2));
            #pragma unroll
            for (int tn = 0; tn < 4; tn++)
                mma16816(acc[tm][tn], a0, a1, a2, a3, b0[tn], b1[tn]);
        }

        if (s + 3 < KSTEPS) {
            gemm_load(s + 3, i0, j0, sbA, sbB, aoff, lrow, lseg);
            CP_COMMIT();
        }
    }

    #pragma unroll
    for (int tm = 0; tm < 4; tm++) {
        int r0 = i0 + wr * 64 + tm * 16 + g;
        float xn0 = g_xn[r0], xn1 = g_xn[r0 + 8];
        #pragma unroll
        for (int tn = 0; tn < 4; tn++) {
            int cb = j0 + wc * 32 + tn * 8 + q * 2;
            float yn0 = g_yn[cb], yn1 = g_yn[cb + 1];
            float2 o0, o1;
            o0.x = fmaf(2.f * ALPHA, acc[tm][tn][0], -ALPHA * (xn0 + yn0));
            o0.y = fmaf(2.f * ALPHA, acc[tm][tn][1], -ALPHA * (xn0 + yn1));
            o1.x = fmaf(2.f * ALPHA, acc[tm][tn][2], -ALPHA * (xn1 + yn0));
            o1.y = fmaf(2.f * ALPHA, acc[tm][tn][3], -ALPHA * (xn1 + yn1));
            *(float2*)(g_logK0 + (size_t)r0 * Mm + cb)       = o0;
            *(float2*)(g_logK0 + (size_t)(r0 + 8) * Mm + cb) = o1;
        }
    }
}

// ============ persistent Sinkhorn (+ fused transp/loss) ============

__device__ __forceinline__ void gridbar(unsigned& epoch) {
    epoch += NB;
    __syncthreads();
    if (threadIdx.x == 0) {
        __threadfence();
        atomicAdd((unsigned*)&g_barcnt, 1u);
        while (g_barcnt < epoch) { }
        __threadfence();
    }
    __syncthreads();
}

// online-LSE update: (m, s) <- combine with value t
#define ONLINE(m, s, t) do { \
    float _n = fmaxf(m, t); \
    s = fmaf(s, __expf((m) - _n), __expf((t) - _n)); \
    m = _n; } while (0)

// combine two (m, s) LSE pairs into the first
__device__ __forceinline__ void lse_comb(float& m, float& s, float om, float os) {
    float nm = fmaxf(m, om);
    s = fmaf(s, __expf(m - nm), os * __expf(om - nm));
    m = nm;
}

#define SHFL_ADD4(m, o) do { \
    m.x += __shfl_xor_sync(0xffffffffu, m.x, o); \
    m.y += __shfl_xor_sync(0xffffffffu, m.y, o); \
    m.z += __shfl_xor_sync(0xffffffffu, m.z, o); \
    m.w += __shfl_xor_sync(0xffffffffu, m.w, o); } while (0)
#define SHFL_LSE4(m, s, o) do { \
    float _om, _os; \
    _om = __shfl_xor_sync(0xffffffffu, m.x, o); _os = __shfl_xor_sync(0xffffffffu, s.x, o); lse_comb(m.x, s.x, _om, _os); \
    _om = __shfl_xor_sync(0xffffffffu, m.y, o); _os = __shfl_xor_sync(0xffffffffu, s.y, o); lse_comb(m.y, s.y, _om, _os); \
    _om = __shfl_xor_sync(0xffffffffu, m.z, o); _os = __shfl_xor_sync(0xffffffffu, s.z, o); lse_comb(m.z, s.z, _om, _os); \
    _om = __shfl_xor_sync(0xffffffffu, m.w, o); _os = __shfl_xor_sync(0xffffffffu, s.w, o); lse_comb(m.w, s.w, _om, _os); } while (0)

// logv <- LOG_B - lse_i(logK0 + logu). ONE matrix read (online LSE).
__device__ __forceinline__ void colpass(float* su) {
    int tid = threadIdx.x;
    su[tid] = g_logu[tid];
    __syncthreads();
    int g = blockIdx.x * NT + tid;
    int cg = g >> 2, p = g & 3;
    const float4* col = (const float4*)g_logK0 + cg;
    int ibase = p * 64;

    float4 m = {NEGBIG, NEGBIG, NEGBIG, NEGBIG};
    float4 s = {0.f, 0.f, 0.f, 0.f};
    #pragma unroll 8
    for (int ii = 0; ii < 64; ii++) {
        float4 v = col[(size_t)(ibase + ii) * (Mm / 4)];
        float u = su[ibase + ii];
        ONLINE(m.x, s.x, v.x + u); ONLINE(m.y, s.y, v.y + u);
        ONLINE(m.z, s.z, v.z + u); ONLINE(m.w, s.w, v.w + u);
    }
    SHFL_LSE4(m, s, 1); SHFL_LSE4(m, s, 2);

    if (p == 0) {
        float4 o;
        o.x = LOG_B - (m.x + logf(s.x));
        o.y = LOG_B - (m.y + logf(s.y));
        o.z = LOG_B - (m.z + logf(s.z));
        o.w = LOG_B - (m.w + logf(s.w));
        ((float4*)g_logv)[cg] = o;
    }
    __syncthreads();
}

// logu <- LOG_A - lse_j(logK0 + logv). ONE matrix read (online LSE), 2 rows/block.
__device__ __forceinline__ void rowpass(float* red) {
    int tid = threadIdx.x;
    int i0 = blockIdx.x * 2;
    const float4* r0 = (const float4*)(g_logK0 + (size_t)i0 * Mm);
    const float4* r1 = (const float4*)(g_logK0 + (size_t)(i0 + 1) * Mm);
    const float4* vv = (const float4*)g_logv;
    const int NV = Mm / 4;

    float4 m0 = {NEGBIG, NEGBIG, NEGBIG, NEGBIG}, s0 = {0.f, 0.f, 0.f, 0.f};
    float4 m1 = m0, s1 = s0;
    #pragma unroll 4
    for (int j = tid; j < NV; j += NT) {
        float4 v = vv[j], a = r0[j], b = r1[j];
        ONLINE(m0.x, s0.x, a.x + v.x); ONLINE(m0.y, s0.y, a.y + v.y);
        ONLINE(m0.z, s0.z, a.z + v.z); ONLINE(m0.w, s0.w, a.w + v.w);
        ONLINE(m1.x, s1.x, b.x + v.x); ONLINE(m1.y, s1.y, b.y + v.y);
        ONLINE(m1.z, s1.z, b.z + v.z); ONLINE(m1.w, s1.w, b.w + v.w);
    }
    float M0 = m0.x, S0 = s0.x;
    lse_comb(M0, S0, m0.y, s0.y); lse_comb(M0, S0, m0.z, s0.z); lse_comb(M0, S0, m0.w, s0.w);
    float M1 = m1.x, S1 = s1.x;
    lse_comb(M1, S1, m1.y, s1.y); lse_comb(M1, S1, m1.z, s1.z); lse_comb(M1, S1, m1.w, s1.w);
    #pragma unroll
    for (int o = 16; o; o >>= 1) {
        float om, os;
        om = __shfl_xor_sync(0xffffffffu, M0, o); os = __shfl_xor_sync(0xffffffffu, S0, o);
        lse_comb(M0, S0, om, os);
        om = __shfl_xor_sync(0xffffffffu, M1, o); os = __shfl_xor_sync(0xffffffffu, S1, o);
        lse_comb(M1, S1, om, os);
    }
    int w = tid >> 5;
    if ((tid & 31) == 0) {
        red[w] = M0; red[8 + w] = S0; red[16 + w] = M1; red[24 + w] = S1;
    }
    __syncthreads();
    if (tid == 0) {
        float Ma = red[0], Sa = red[8];
        float Mb = red[16], Sb = red[24];
        #pragma unroll
        for (int k = 1; k < 8; k++) {
            lse_comb(Ma, Sa, red[k], red[8 + k]);
            lse_comb(Mb, Sb, red[16 + k], red[24 + k]);
        }
        g_logu[i0]     = LOG_A - (Ma + logf(Sa));
        g_logu[i0 + 1] = LOG_A - (Mb + logf(Sb));
    }
    __syncthreads();
}

// Column-marginal error + transp + loss, ONE matrix read, no max-shift.
__device__ __forceinline__ float colerr_transp(float* su, float* out, int do_err) {
    int tid = threadIdx.x;
    su[tid] = g_cumu[tid] + g_logu[tid];
    __syncthreads();
    int g = blockIdx.x * NT + tid;
    int cg = g >> 2, p = g & 3;
    const float4* col = (const float4*)g_logK0 + cg;
    float* outp = out + 1 + cg * 4;
    int ibase = p * 64;

    float4 cv = ((const float4*)g_cumv)[cg];
    float4 lv = ((const float4*)g_logv)[cg];
    float4 sv;
    sv.x = cv.x + lv.x; sv.y = cv.y + lv.y; sv.z = cv.z + lv.z; sv.w = cv.w + lv.w;

    float4 s = {0.f, 0.f, 0.f, 0.f};
    float part = 0.f;
    #pragma unroll 4
    for (int ii = 0; ii < 64; ii++) {
        float4 v = col[(size_t)(ibase + ii) * (Mm / 4)];
        float u = su[ibase + ii];
        float4 tr;
        tr.x = __expf(v.x + u + sv.x); tr.y = __expf(v.y + u + sv.y);
        tr.z = __expf(v.z + u + sv.z); tr.w = __expf(v.w + u + sv.w);
        s.x += tr.x; s.y += tr.y; s.z += tr.z; s.w += tr.w;
        float* op = outp + (size_t)(ibase + ii) * Mm;
        op[0] = tr.x; op[1] = tr.y; op[2] = tr.z; op[3] = tr.w;
        part = fmaf(tr.x, v.x, fmaf(tr.y, v.y, fmaf(tr.z, v.z, fmaf(tr.w, v.w, part))));
    }
    SHFL_ADD4(s, 1); SHFL_ADD4(s, 2);

    if (do_err) {
        float d = fmaxf(fmaxf(fabsf(s.x - BB), fabsf(s.y - BB)),
                        fmaxf(fabsf(s.z - BB), fabsf(s.w - BB)));
        #pragma unroll
        for (int o = 16; o; o >>= 1)
            d = fmaxf(d, __shfl_xor_sync(0xffffffffu, d, o));
        if ((tid & 31) == 0) atomicMax(&g_errbits, __float_as_uint(d));
    }
    __syncthreads();
    return part * (-1.f / ALPHA);
}

__global__ void __launch_bounds__(NT, 1) k_sink(float* out) {
    __shared__ float su[Nn];
    __shared__ float red[32];
    unsigned epoch = 0;
    int tid = threadIdx.x;
    int gtid = blockIdx.x * NT + tid;
    float part = 0.f;
    int conv = 0;

    for (int t = 1; t <= 100; t++) {
        colpass(su);
        gridbar(epoch);
        rowpass(red);
        gridbar(epoch);
        if (t % 50 == 1) {
            part = colerr_transp(su, out, 1);       // speculative transp + err
            gridbar(epoch);
            conv = (__uint_as_float(*(volatile unsigned*)&g_errbits) <= STOPTHR);
            if (conv) break;
            g_cumv[gtid] += g_logv[gtid]; g_logv[gtid] = 0.f;
            if (gtid < Nn) { g_cumu[gtid] += g_logu[gtid]; g_logu[gtid] = 0.f; }
            if (gtid == 0) g_errbits = 0u;
            gridbar(epoch);
        }
    }
    if (!conv)
        part = colerr_transp(su, out, 0);           // final state transp

    #pragma unroll
    for (int o = 16; o; o >>= 1) part += __shfl_xor_sync(0xffffffffu, part, o);
    if ((tid & 31) == 0) red[tid >> 5] = part;
    __syncthreads();
    if (tid == 0) {
        float S = 0.f;
        #pragma unroll
        for (int w = 0; w < 8; w++) S += red[w];
        atomicAdd(out, S);
    }
}

// ---------------- launch ----------------
extern "C" void kernel_launch(void* const* d_in, const int* in_sizes, int n_in,
                              void* d_out, int out_size) {
    const float* x = (const float*)d_in[0];   // [256, 384]
    const float* y = (const float*)d_in[1];   // [32768, 384]
    float* out = (float*)d_out;               // [0]=loss, [1..]=transp

    __half *xh, *xl, *yh, *yl;
    float *xn, *yn;
    cudaGetSymbolAddress((void**)&xh, g_xh);
    cudaGetSymbolAddress((void**)&xl, g_xl);
    cudaGetSymbolAddress((void**)&yh, g_yh);
    cudaGetSymbolAddress((void**)&yl, g_yl);
    cudaGetSymbolAddress((void**)&xn, g_xn);
    cudaGetSymbolAddress((void**)&yn, g_yn);

    k_init<<<(Mm + 255) / 256, 256>>>(out);
    k_prep<<<Nn / 8, 256>>>(x, xh, xl, xn);
    k_prep<<<Mm / 8, 256>>>(y, yh, yl, yn);
    k_gemm_mma<<<dim3(Mm / 128, Nn / 128), 256>>>();
    k_sink<<<NB, NT>>>(out);
}